// round 11
// baseline (speedup 1.0000x reference)
#include <cuda_runtime.h>
#include <cstdint>
#include <climits>

#define B        4
#define NLID     16384
#define NIMG     4096
#define NTOK     20480
#define C        256
#define NV       6
#define TOTAL    (B*NTOK)        // 81920
#define STHR     512
#define SWARP    16
#define IPT      2
#define BLK_ITEMS 1024
#define NBLK_SEG 20              // blocks per segment
#define NBLKS    80
#define CNT_SEG  (256*NBLK_SEG)  // 5120
#define CPT      20              // == NBLK_SEG (thread tid<256 owns digit tid)

// ---------------- static device scratch (no allocations) ----------------
__device__ unsigned long long g_e0[TOTAL];
__device__ unsigned long long g_e1[TOTAL];
__device__ unsigned int       g_cnt0[B * CNT_SEG];
__device__ unsigned int       g_cnt1[B * CNT_SEG];
__device__ unsigned int       g_cnt2[B * CNT_SEG];
__device__ int                g_bmin[B][NBLK_SEG][3];
__device__ int                g_bmax[B][NBLK_SEG][3];
__device__ unsigned int       g_ctrs[B * 32];   // per-segment arrival counter (128B stride)
__device__ unsigned int       g_bases[B * 32];  // per-segment per-launch base

// ---------------- 3x3 inverse via adjugate in double ----------------
__device__ __forceinline__ void inv3(const float* a, float* o) {
    double m[9];
#pragma unroll
    for (int i = 0; i < 9; i++) m[i] = (double)a[i];
    double c00 =   m[4]*m[8] - m[5]*m[7];
    double c01 = -(m[3]*m[8] - m[5]*m[6]);
    double c02 =   m[3]*m[7] - m[4]*m[6];
    double det = m[0]*c00 + m[1]*c01 + m[2]*c02;
    double id  = 1.0 / det;
    o[0] = (float)( c00 * id);
    o[1] = (float)(-(m[1]*m[8] - m[2]*m[7]) * id);
    o[2] = (float)( (m[1]*m[5] - m[2]*m[4]) * id);
    o[3] = (float)( c01 * id);
    o[4] = (float)( (m[0]*m[8] - m[2]*m[6]) * id);
    o[5] = (float)(-(m[0]*m[5] - m[2]*m[3]) * id);
    o[6] = (float)( c02 * id);
    o[7] = (float)(-(m[0]*m[7] - m[1]*m[6]) * id);
    o[8] = (float)( (m[0]*m[4] - m[1]*m[3]) * id);
}

// ---------------- split per-segment barrier (20 blocks; all co-resident) ----------------
__device__ __forceinline__ void seg_arrive(int seg) {
    __syncthreads();
    if (threadIdx.x == 0) {
        __threadfence();
        atomicAdd(&g_ctrs[seg * 32], 1u);
    }
}
__device__ __forceinline__ void seg_wait(int seg, unsigned base, unsigned idx) {
    if (threadIdx.x == 0) {
        unsigned target = idx * NBLK_SEG;
        while ((*(volatile unsigned*)&g_ctrs[seg * 32]) - base < target) { }
        __threadfence();
    }
    __syncthreads();
}

// ---------------- stable per-warp ranking via match_any (warp-local only) ----------------
__device__ __forceinline__ void rank_items(
    const unsigned long long e[IPT], int shift, int w, int lane,
    unsigned (*whist)[256], unsigned dg[IPT], unsigned rk[IPT])
{
#pragma unroll
    for (int k = 0; k < 8; k++) whist[w][lane + 32 * k] = 0;   // own row only
    __syncwarp();
#pragma unroll
    for (int it = 0; it < IPT; it++) {
        dg[it] = (unsigned)(e[it] >> shift) & 255u;
        unsigned mset = __match_any_sync(0xFFFFFFFFu, dg[it]);
        unsigned before = whist[w][dg[it]];
        rk[it] = before + __popc(mset & ((1u << lane) - 1u));
        __syncwarp();
        if ((mset & (0u - mset)) == (1u << lane))
            whist[w][dg[it]] = before + __popc(mset);
        __syncwarp();
    }
}

// ---------------- scan + exclusive + scatter (2 syncthreads total) ----------------
__device__ __forceinline__ void pass_finish(
    const unsigned long long e[IPT], const unsigned dg[IPT], const unsigned rk[IPT],
    unsigned v[CPT], int bib, int w, int lane, int tid,
    unsigned long long* __restrict__ dst_seg,
    unsigned* __restrict__ cnt_next_seg, int shift_next,
    unsigned (*whist)[256], unsigned* wsum)
{
    unsigned s = 0, sum = 0;
    if (tid < 256) {
        // thread tid owns digit tid: exclusive over its 20 block counts
#pragma unroll
        for (int k = 0; k < CPT; k++) { unsigned t = v[k]; v[k] = sum; sum += t; }
        s = sum;
#pragma unroll
        for (int off = 1; off < 32; off <<= 1) {
            unsigned n = __shfl_up_sync(0xFFFFFFFFu, s, off);
            if (lane >= off) s += n;
        }
        if (lane == 31) wsum[w] = s;     // w in 0..7
    }
    __syncthreads();                     // S1: ranking whist + wsum complete

    if (tid < 256) {
        unsigned base_w = 0;
#pragma unroll
        for (int i = 0; i < 8; i++) { unsigned t = wsum[i]; if (i < w) base_w += t; }
        unsigned run = base_w + (s - sum) + v[bib];
#pragma unroll
        for (int ww = 0; ww < SWARP; ww++) {
            unsigned t = whist[ww][tid];
            whist[ww][tid] = run;
            run += t;
        }
    }
    __syncthreads();                     // S2: publish absolute offsets

#pragma unroll
    for (int it = 0; it < IPT; it++) {
        unsigned pos = whist[w][dg[it]] + rk[it];
        dst_seg[pos] = e[it];
        if (cnt_next_seg) {
            unsigned d2 = (unsigned)(e[it] >> shift_next) & 255u;
            atomicAdd(&cnt_next_seg[d2 * NBLK_SEG + (pos >> 10)], 1u);
        }
    }
}

// ---------------- mega kernel: geometry + keys + full 3-pass sort ----------------
__global__ void __launch_bounds__(STHR, 1) mega_kernel(
    const float* __restrict__ lidar_coords,
    const float* __restrict__ img_kuvd,
    const float* __restrict__ Kmat,
    const float* __restrict__ Tmat,
    const float* __restrict__ Rmat,
    const float* __restrict__ ptrans,
    const unsigned char* __restrict__ lmask,
    const unsigned char* __restrict__ imask)
{
    __shared__ float    sInvK[NV * 9], sInvR[NV * 9];
    __shared__ int      smin[3], smax[3];
    __shared__ unsigned whist[SWARP][256];
    __shared__ unsigned wsum[8];
    __shared__ unsigned hist[256];

    int tid = threadIdx.x, lane = tid & 31, w = tid >> 5;
    int blk = blockIdx.x, seg = blk / NBLK_SEG, bib = blk % NBLK_SEG;
    unsigned base = g_bases[seg * 32];

    if (tid < 3) { smin[tid] = INT_MAX; smax[tid] = INT_MIN; }
    if (tid < 256) hist[tid] = 0;
    if (tid < NV)
        inv3(Kmat + ((size_t)seg * NV + tid) * 9, sInvK + tid * 9);
    else if (tid < 2 * NV)
        inv3(Rmat + ((size_t)seg * NV + (tid - NV)) * 9, sInvR + (tid - NV) * 9);
    {
        int z = blk * STHR + tid;
        if (z < B * CNT_SEG) { g_cnt1[z] = 0; g_cnt2[z] = 0; }
    }
    __syncthreads();

    // ---- Phase A: quantize own 1024 items (registers) + block min/max ----
    int q0r[IPT], q1r[IPT], q2r[IPT];
    int mn0 = INT_MAX, mn1 = INT_MAX, mn2 = INT_MAX;
    int mx0 = INT_MIN, mx1 = INT_MIN, mx2 = INT_MIN;
#pragma unroll
    for (int it = 0; it < IPT; it++) {
        int i = bib * BLK_ITEMS + w * (IPT * 32) + it * 32 + lane;
        float x, y, z;
        if (i < NLID) {
            const float* c = lidar_coords + ((size_t)seg * NLID + i) * 3;
            x = c[0]; y = c[1]; z = c[2];
        } else {
            int j = i - NLID;
            const float* kv = img_kuvd + ((size_t)seg * NIMG + j) * 4;
            int cam = (int)kv[0];
            float u = kv[1], v = kv[2], D = kv[3];
            const float* tt = ptrans + (seg * NV + cam) * 3;
            float u1 = u - tt[0], v1 = v - tt[1], w1 = 1.0f - tt[2];
            const float* iR = sInvR + cam * 9;
            float rx = fmaf(iR[0], u1, fmaf(iR[1], v1, iR[2] * w1));
            float ry = fmaf(iR[3], u1, fmaf(iR[4], v1, iR[5] * w1));
            const float* iK = sInvK + cam * 9;
            float cx = fmaf(iK[0], rx, fmaf(iK[1], ry, iK[2])) * D;
            float cy = fmaf(iK[3], rx, fmaf(iK[4], ry, iK[5])) * D;
            float cz = fmaf(iK[6], rx, fmaf(iK[7], ry, iK[8])) * D;
            const float* Tm = Tmat + (size_t)(seg * NV + cam) * 16;
            x = fmaf(Tm[0], cx, fmaf(Tm[1], cy, fmaf(Tm[2],  cz, Tm[3])));
            y = fmaf(Tm[4], cx, fmaf(Tm[5], cy, fmaf(Tm[6],  cz, Tm[7])));
            z = fmaf(Tm[8], cx, fmaf(Tm[9], cy, fmaf(Tm[10], cz, Tm[11])));
        }
        int q0 = (int)floorf(x), q1 = (int)floorf(y), q2 = (int)floorf(z);
        q0r[it] = q0; q1r[it] = q1; q2r[it] = q2;
        mn0 = min(mn0, q0); mx0 = max(mx0, q0);
        mn1 = min(mn1, q1); mx1 = max(mx1, q1);
        mn2 = min(mn2, q2); mx2 = max(mx2, q2);
    }
#pragma unroll
    for (int off = 16; off; off >>= 1) {
        mn0 = min(mn0, __shfl_xor_sync(0xFFFFFFFFu, mn0, off));
        mn1 = min(mn1, __shfl_xor_sync(0xFFFFFFFFu, mn1, off));
        mn2 = min(mn2, __shfl_xor_sync(0xFFFFFFFFu, mn2, off));
        mx0 = max(mx0, __shfl_xor_sync(0xFFFFFFFFu, mx0, off));
        mx1 = max(mx1, __shfl_xor_sync(0xFFFFFFFFu, mx1, off));
        mx2 = max(mx2, __shfl_xor_sync(0xFFFFFFFFu, mx2, off));
    }
    if (lane == 0) {
        atomicMin(&smin[0], mn0); atomicMax(&smax[0], mx0);
        atomicMin(&smin[1], mn1); atomicMax(&smax[1], mx1);
        atomicMin(&smin[2], mn2); atomicMax(&smax[2], mx2);
    }
    __syncthreads();
    if (tid < 3) {
        g_bmin[seg][bib][tid] = smin[tid];
        g_bmax[seg][bib][tid] = smax[tid];
    }

    seg_arrive(seg); seg_wait(seg, base, 1);

    // ---- Phase B: segment min/max + keys (registers) + pass-0 histogram ----
    if (w < 6) {
        int d = w % 3;
        bool ismax = (w >= 3);
        int val = ismax ? INT_MIN : INT_MAX;
        if (lane < NBLK_SEG)
            val = ismax ? __ldcg(&g_bmax[seg][lane][d]) : __ldcg(&g_bmin[seg][lane][d]);
#pragma unroll
        for (int off = 16; off; off >>= 1) {
            int o = __shfl_xor_sync(0xFFFFFFFFu, val, off);
            val = ismax ? max(val, o) : min(val, o);
        }
        if (lane == 0) { if (ismax) smax[d] = val; else smin[d] = val; }
    }
    __syncthreads();
    int m0 = smin[0], m1 = smin[1], m2 = smin[2];
    int M1 = smax[1] - m1, M2 = smax[2] - m2;

    unsigned long long e[IPT];
#pragma unroll
    for (int it = 0; it < IPT; it++) {
        int i = bib * BLK_ITEMS + w * (IPT * 32) + it * 32 + lane;
        int d0 = q0r[it] - m0, d1 = q1r[it] - m1, d2 = q2r[it] - m2;
        int s1 = (d0 & 1)        ? (M1 - d1) : d1;
        int s2 = ((d0 + d1) & 1) ? (M2 - d2) : d2;
        bool msk = (i < NLID) ? (lmask[(size_t)seg * NLID + i] != 0)
                              : (imask[(size_t)seg * NIMG + (i - NLID)] != 0);
        unsigned key = msk ? 0xFFFFFFu
                           : (((unsigned)d0 << 16) | ((unsigned)s1 << 8) | (unsigned)s2);
        e[it] = ((unsigned long long)key << 16) | (unsigned)i;
        atomicAdd(&hist[key & 255u], 1u);
    }
    __syncthreads();
    if (tid < 256)
        g_cnt0[seg * CNT_SEG + tid * NBLK_SEG + bib] = hist[tid];

    // ---- Phase C: pass 0 — rank in barrier shadow, then scan+scatter ----
    unsigned dg[IPT], rk[IPT];
    seg_arrive(seg);
    rank_items(e, 16, w, lane, whist, dg, rk);      // block-local, overlaps barrier
    seg_wait(seg, base, 2);

    unsigned v[CPT];
    if (tid < 256) {
        const unsigned* cnt = g_cnt0 + seg * CNT_SEG;
#pragma unroll
        for (int k = 0; k < CPT; k++) v[k] = __ldcg(&cnt[tid * CPT + k]);
    }
    pass_finish(e, dg, rk, v, bib, w, lane, tid, g_e1 + seg * NTOK,
                g_cnt1 + seg * CNT_SEG, 24, whist, wsum);

    seg_arrive(seg); seg_wait(seg, base, 3);

    // ---- Phase D: pass 1 ----
#pragma unroll
    for (int it = 0; it < IPT; it++)
        e[it] = __ldcg(&g_e1[seg * NTOK + bib * BLK_ITEMS + w * (IPT * 32) + it * 32 + lane]);
    if (tid < 256) {
        const unsigned* cnt = g_cnt1 + seg * CNT_SEG;
#pragma unroll
        for (int k = 0; k < CPT; k++) v[k] = __ldcg(&cnt[tid * CPT + k]);
    }
    rank_items(e, 24, w, lane, whist, dg, rk);
    pass_finish(e, dg, rk, v, bib, w, lane, tid, g_e0 + seg * NTOK,
                g_cnt2 + seg * CNT_SEG, 32, whist, wsum);

    seg_arrive(seg); seg_wait(seg, base, 4);

    // ---- Phase E: pass 2 (final -> g_e1) ----
#pragma unroll
    for (int it = 0; it < IPT; it++)
        e[it] = __ldcg(&g_e0[seg * NTOK + bib * BLK_ITEMS + w * (IPT * 32) + it * 32 + lane]);
    if (tid < 256) {
        const unsigned* cnt = g_cnt2 + seg * CNT_SEG;
#pragma unroll
        for (int k = 0; k < CPT; k++) v[k] = __ldcg(&cnt[tid * CPT + k]);
    }
    rank_items(e, 32, w, lane, whist, dg, rk);
    pass_finish(e, dg, rk, v, bib, w, lane, tid, g_e1 + seg * NTOK,
                nullptr, 0, whist, wsum);

    if (bib == 0 && tid == 0) g_bases[seg * 32] = base + 4u * NBLK_SEG;
}

// ---------------- dummy (keeps ncu capture slot #4 on mega) ----------------
__global__ void dummy_kernel() {}

// ---------------- gather: 8 threads/row, 8 independent float4 each (MLP 8) ----------------
__global__ void gather_kernel(const float* __restrict__ lidar_tokens,
                              const float* __restrict__ img_tokens,
                              const unsigned char* __restrict__ lmask,
                              const unsigned char* __restrict__ imask,
                              float* __restrict__ out, int out_size) {
    int gid = blockIdx.x * blockDim.x + threadIdx.x;   // TOTAL*8 threads
    int r = gid >> 3;
    int c = gid & 7;
    if (r >= TOTAL) return;
    unsigned long long e = g_e1[r];
    int idx = (int)(e & 0xFFFFull);
    int b = r / NTOK;
    const float4* src;
    if (idx < NLID)
        src = (const float4*)(lidar_tokens + ((size_t)b * NLID + idx) * C);
    else
        src = (const float4*)(img_tokens + ((size_t)b * NIMG + (idx - NLID)) * C);
    float4* d = (float4*)out + (size_t)r * 64;
#pragma unroll
    for (int k = 0; k < 8; k++)
        d[c + 8 * k] = src[c + 8 * k];

    if (c == 0) {
        size_t idx_base  = (size_t)TOTAL * C;
        size_t mask_base = idx_base + TOTAL;
        out[idx_base + r] = (float)idx;
        bool m = (idx < NLID) ? (lmask[(size_t)b * NLID + idx] != 0)
                              : (imask[(size_t)b * NIMG + (idx - NLID)] != 0);
        out[mask_base + r] = m ? 1.0f : 0.0f;
        if (r == 0) {
            size_t tail = mask_base + TOTAL;
            if ((size_t)out_size >= tail + 2) {
                out[tail + 0] = 16384.0f;
                out[tail + 1] = 1.0f;
            }
        }
    }
}

// ---------------- launch ----------------
extern "C" void kernel_launch(void* const* d_in, const int* in_sizes, int n_in,
                              void* d_out, int out_size) {
    const float* lidar_tokens = (const float*)d_in[0];
    const float* lidar_coords = (const float*)d_in[1];
    const float* img_tokens   = (const float*)d_in[2];
    const float* img_kuvd     = (const float*)d_in[3];
    const float* Km           = (const float*)d_in[4];
    const float* Tm           = (const float*)d_in[5];
    const float* Rm           = (const float*)d_in[6];
    const float* ptrans       = (const float*)d_in[7];
    const unsigned char* lm   = (const unsigned char*)d_in[8];
    const unsigned char* im   = (const unsigned char*)d_in[9];
    float* out = (float*)d_out;

    mega_kernel<<<NBLKS, STHR>>>(lidar_coords, img_kuvd, Km, Tm, Rm, ptrans, lm, im);
    dummy_kernel<<<1, 32>>>();   // parity shim: keeps ncu slot #4 on mega
    gather_kernel<<<(TOTAL * 8) / 256, 256>>>(lidar_tokens, img_tokens, lm, im,
                                              out, out_size);
}

// round 12
// speedup vs baseline: 1.2490x; 1.2490x over previous
#include <cuda_runtime.h>
#include <cstdint>
#include <climits>

#define B        4
#define NLID     16384
#define NIMG     4096
#define NTOK     20480
#define C        256
#define NV       6
#define TOTAL    (B*NTOK)        // 81920
#define STHR     256
#define SWARP    8
#define IPT      4
#define BLK_ITEMS 1024
#define NBLK_SEG 20              // blocks per segment
#define NBLKS    80
#define CNT_SEG  (256*NBLK_SEG)  // 5120
#define CPT      20              // == NBLK_SEG

// ---------------- static device scratch (no allocations) ----------------
__device__ unsigned long long g_e0[TOTAL];
__device__ unsigned long long g_e1[TOTAL];
__device__ unsigned int       g_inv[TOTAL];     // source idx -> sorted pos (per segment)
__device__ unsigned int       g_cnt0[B * CNT_SEG];
__device__ unsigned int       g_cnt1[B * CNT_SEG];
__device__ unsigned int       g_cnt2[B * CNT_SEG];
__device__ int                g_bmin[B][NBLK_SEG][3];
__device__ int                g_bmax[B][NBLK_SEG][3];
__device__ unsigned int       g_ctrs[B * 32];   // per-segment arrival counter (128B stride)
__device__ unsigned int       g_bases[B * 32];  // per-segment per-launch base

// ---------------- 3x3 inverse via adjugate in double ----------------
__device__ __forceinline__ void inv3(const float* a, float* o) {
    double m[9];
#pragma unroll
    for (int i = 0; i < 9; i++) m[i] = (double)a[i];
    double c00 =   m[4]*m[8] - m[5]*m[7];
    double c01 = -(m[3]*m[8] - m[5]*m[6]);
    double c02 =   m[3]*m[7] - m[4]*m[6];
    double det = m[0]*c00 + m[1]*c01 + m[2]*c02;
    double id  = 1.0 / det;
    o[0] = (float)( c00 * id);
    o[1] = (float)(-(m[1]*m[8] - m[2]*m[7]) * id);
    o[2] = (float)( (m[1]*m[5] - m[2]*m[4]) * id);
    o[3] = (float)( c01 * id);
    o[4] = (float)( (m[0]*m[8] - m[2]*m[6]) * id);
    o[5] = (float)(-(m[0]*m[5] - m[2]*m[3]) * id);
    o[6] = (float)( c02 * id);
    o[7] = (float)(-(m[0]*m[7] - m[1]*m[6]) * id);
    o[8] = (float)( (m[0]*m[4] - m[1]*m[3]) * id);
}

// ---------------- split per-segment barrier (20 blocks; all co-resident) ----------------
__device__ __forceinline__ void seg_arrive(int seg) {
    __syncthreads();
    if (threadIdx.x == 0) {
        __threadfence();
        atomicAdd(&g_ctrs[seg * 32], 1u);
    }
}
__device__ __forceinline__ void seg_wait(int seg, unsigned base, unsigned idx) {
    if (threadIdx.x == 0) {
        unsigned target = idx * NBLK_SEG;
        while ((*(volatile unsigned*)&g_ctrs[seg * 32]) - base < target) { }
        __threadfence();
    }
    __syncthreads();
}

// ---------------- stable per-warp ranking via match_any (warp-local only) ----------------
__device__ __forceinline__ void rank_items(
    const unsigned long long e[IPT], int shift, int w, int lane,
    unsigned (*whist)[256], unsigned dg[IPT], unsigned rk[IPT])
{
#pragma unroll
    for (int k = 0; k < 8; k++) whist[w][lane + 32 * k] = 0;   // own row only
    __syncwarp();
#pragma unroll
    for (int it = 0; it < IPT; it++) {
        dg[it] = (unsigned)(e[it] >> shift) & 255u;
        unsigned mset = __match_any_sync(0xFFFFFFFFu, dg[it]);
        unsigned before = whist[w][dg[it]];
        rk[it] = before + __popc(mset & ((1u << lane) - 1u));
        __syncwarp();
        if ((mset & (0u - mset)) == (1u << lane))
            whist[w][dg[it]] = before + __popc(mset);
        __syncwarp();
    }
}

// ---------------- scan + exclusive + scatter (2 syncthreads total) ----------------
// dst_seg != nullptr: write sorted entries; inv_seg != nullptr: write idx->pos map.
__device__ __forceinline__ void pass_finish(
    const unsigned long long e[IPT], const unsigned dg[IPT], const unsigned rk[IPT],
    unsigned v[CPT], int bib, int w, int lane, int tid,
    unsigned long long* __restrict__ dst_seg,
    unsigned* __restrict__ inv_seg,
    unsigned* __restrict__ cnt_next_seg, int shift_next,
    unsigned (*whist)[256], unsigned* wsum)
{
    // thread tid owns digit tid: exclusive over its 20 block counts
    unsigned sum = 0;
#pragma unroll
    for (int k = 0; k < CPT; k++) { unsigned t = v[k]; v[k] = sum; sum += t; }
    unsigned s = sum;
#pragma unroll
    for (int off = 1; off < 32; off <<= 1) {
        unsigned n = __shfl_up_sync(0xFFFFFFFFu, s, off);
        if (lane >= off) s += n;
    }
    if (lane == 31) wsum[w] = s;
    __syncthreads();                       // S1: ranking whist + wsum complete

    unsigned base_w = 0;
#pragma unroll
    for (int i = 0; i < SWARP; i++) { unsigned t = wsum[i]; if (i < w) base_w += t; }

    unsigned run = base_w + (s - sum) + v[bib];
#pragma unroll
    for (int ww = 0; ww < SWARP; ww++) {
        unsigned t = whist[ww][tid];
        whist[ww][tid] = run;
        run += t;
    }
    __syncthreads();                       // S2: publish absolute offsets

#pragma unroll
    for (int it = 0; it < IPT; it++) {
        unsigned pos = whist[w][dg[it]] + rk[it];
        if (dst_seg) dst_seg[pos] = e[it];
        if (inv_seg) inv_seg[(unsigned)(e[it] & 0xFFFFull)] = pos;
        if (cnt_next_seg) {
            unsigned d2 = (unsigned)(e[it] >> shift_next) & 255u;
            atomicAdd(&cnt_next_seg[d2 * NBLK_SEG + (pos >> 10)], 1u);
        }
    }
}

// ---------------- mega kernel: geometry + keys + full 3-pass sort ----------------
__global__ void __launch_bounds__(STHR, 1) mega_kernel(
    const float* __restrict__ lidar_coords,
    const float* __restrict__ img_kuvd,
    const float* __restrict__ Kmat,
    const float* __restrict__ Tmat,
    const float* __restrict__ Rmat,
    const float* __restrict__ ptrans,
    const unsigned char* __restrict__ lmask,
    const unsigned char* __restrict__ imask)
{
    __shared__ float    sInvK[NV * 9], sInvR[NV * 9];
    __shared__ int      smin[3], smax[3];
    __shared__ unsigned whist[SWARP][256];
    __shared__ unsigned wsum[SWARP];
    __shared__ unsigned hist[256];

    int tid = threadIdx.x, lane = tid & 31, w = tid >> 5;
    int blk = blockIdx.x, seg = blk / NBLK_SEG, bib = blk % NBLK_SEG;
    unsigned base = g_bases[seg * 32];

    if (tid < 3) { smin[tid] = INT_MAX; smax[tid] = INT_MIN; }
    hist[tid] = 0;
    if (tid < NV)
        inv3(Kmat + ((size_t)seg * NV + tid) * 9, sInvK + tid * 9);
    else if (tid < 2 * NV)
        inv3(Rmat + ((size_t)seg * NV + (tid - NV)) * 9, sInvR + (tid - NV) * 9);
    g_cnt1[blk * STHR + tid] = 0;
    g_cnt2[blk * STHR + tid] = 0;
    __syncthreads();

    // ---- Phase A: quantize own 1024 items (registers) + block min/max ----
    int q0r[IPT], q1r[IPT], q2r[IPT];
    int mn0 = INT_MAX, mn1 = INT_MAX, mn2 = INT_MAX;
    int mx0 = INT_MIN, mx1 = INT_MIN, mx2 = INT_MIN;
#pragma unroll
    for (int it = 0; it < IPT; it++) {
        int i = bib * BLK_ITEMS + w * (IPT * 32) + it * 32 + lane;
        float x, y, z;
        if (i < NLID) {
            const float* c = lidar_coords + ((size_t)seg * NLID + i) * 3;
            x = c[0]; y = c[1]; z = c[2];
        } else {
            int j = i - NLID;
            const float* kv = img_kuvd + ((size_t)seg * NIMG + j) * 4;
            int cam = (int)kv[0];
            float u = kv[1], v = kv[2], D = kv[3];
            const float* tt = ptrans + (seg * NV + cam) * 3;
            float u1 = u - tt[0], v1 = v - tt[1], w1 = 1.0f - tt[2];
            const float* iR = sInvR + cam * 9;
            float rx = fmaf(iR[0], u1, fmaf(iR[1], v1, iR[2] * w1));
            float ry = fmaf(iR[3], u1, fmaf(iR[4], v1, iR[5] * w1));
            const float* iK = sInvK + cam * 9;
            float cx = fmaf(iK[0], rx, fmaf(iK[1], ry, iK[2])) * D;
            float cy = fmaf(iK[3], rx, fmaf(iK[4], ry, iK[5])) * D;
            float cz = fmaf(iK[6], rx, fmaf(iK[7], ry, iK[8])) * D;
            const float* Tm = Tmat + (size_t)(seg * NV + cam) * 16;
            x = fmaf(Tm[0], cx, fmaf(Tm[1], cy, fmaf(Tm[2],  cz, Tm[3])));
            y = fmaf(Tm[4], cx, fmaf(Tm[5], cy, fmaf(Tm[6],  cz, Tm[7])));
            z = fmaf(Tm[8], cx, fmaf(Tm[9], cy, fmaf(Tm[10], cz, Tm[11])));
        }
        int q0 = (int)floorf(x), q1 = (int)floorf(y), q2 = (int)floorf(z);
        q0r[it] = q0; q1r[it] = q1; q2r[it] = q2;
        mn0 = min(mn0, q0); mx0 = max(mx0, q0);
        mn1 = min(mn1, q1); mx1 = max(mx1, q1);
        mn2 = min(mn2, q2); mx2 = max(mx2, q2);
    }
#pragma unroll
    for (int off = 16; off; off >>= 1) {
        mn0 = min(mn0, __shfl_xor_sync(0xFFFFFFFFu, mn0, off));
        mn1 = min(mn1, __shfl_xor_sync(0xFFFFFFFFu, mn1, off));
        mn2 = min(mn2, __shfl_xor_sync(0xFFFFFFFFu, mn2, off));
        mx0 = max(mx0, __shfl_xor_sync(0xFFFFFFFFu, mx0, off));
        mx1 = max(mx1, __shfl_xor_sync(0xFFFFFFFFu, mx1, off));
        mx2 = max(mx2, __shfl_xor_sync(0xFFFFFFFFu, mx2, off));
    }
    if (lane == 0) {
        atomicMin(&smin[0], mn0); atomicMax(&smax[0], mx0);
        atomicMin(&smin[1], mn1); atomicMax(&smax[1], mx1);
        atomicMin(&smin[2], mn2); atomicMax(&smax[2], mx2);
    }
    __syncthreads();
    if (tid < 3) {
        g_bmin[seg][bib][tid] = smin[tid];
        g_bmax[seg][bib][tid] = smax[tid];
    }

    seg_arrive(seg); seg_wait(seg, base, 1);

    // ---- Phase B: segment min/max + keys (registers) + pass-0 histogram ----
    if (w < 6) {
        int d = w % 3;
        bool ismax = (w >= 3);
        int val = ismax ? INT_MIN : INT_MAX;
        if (lane < NBLK_SEG)
            val = ismax ? __ldcg(&g_bmax[seg][lane][d]) : __ldcg(&g_bmin[seg][lane][d]);
#pragma unroll
        for (int off = 16; off; off >>= 1) {
            int o = __shfl_xor_sync(0xFFFFFFFFu, val, off);
            val = ismax ? max(val, o) : min(val, o);
        }
        if (lane == 0) { if (ismax) smax[d] = val; else smin[d] = val; }
    }
    __syncthreads();
    int m0 = smin[0], m1 = smin[1], m2 = smin[2];
    int M1 = smax[1] - m1, M2 = smax[2] - m2;

    unsigned long long e[IPT];
#pragma unroll
    for (int it = 0; it < IPT; it++) {
        int i = bib * BLK_ITEMS + w * (IPT * 32) + it * 32 + lane;
        int d0 = q0r[it] - m0, d1 = q1r[it] - m1, d2 = q2r[it] - m2;
        int s1 = (d0 & 1)        ? (M1 - d1) : d1;
        int s2 = ((d0 + d1) & 1) ? (M2 - d2) : d2;
        bool msk = (i < NLID) ? (lmask[(size_t)seg * NLID + i] != 0)
                              : (imask[(size_t)seg * NIMG + (i - NLID)] != 0);
        unsigned key = msk ? 0xFFFFFFu
                           : (((unsigned)d0 << 16) | ((unsigned)s1 << 8) | (unsigned)s2);
        e[it] = ((unsigned long long)key << 16) | (unsigned)i;
        atomicAdd(&hist[key & 255u], 1u);
    }
    __syncthreads();
    g_cnt0[seg * CNT_SEG + tid * NBLK_SEG + bib] = hist[tid];

    // ---- Phase C: pass 0 — rank in barrier shadow, then scan+scatter ----
    unsigned dg[IPT], rk[IPT];
    seg_arrive(seg);
    rank_items(e, 16, w, lane, whist, dg, rk);      // block-local, overlaps barrier
    seg_wait(seg, base, 2);

    unsigned v[CPT];
    {
        const unsigned* cnt = g_cnt0 + seg * CNT_SEG;
#pragma unroll
        for (int k = 0; k < CPT; k++) v[k] = __ldcg(&cnt[tid * CPT + k]);
    }
    pass_finish(e, dg, rk, v, bib, w, lane, tid, g_e1 + seg * NTOK, nullptr,
                g_cnt1 + seg * CNT_SEG, 24, whist, wsum);

    seg_arrive(seg); seg_wait(seg, base, 3);

    // ---- Phase D: pass 1 ----
#pragma unroll
    for (int it = 0; it < IPT; it++)
        e[it] = __ldcg(&g_e1[seg * NTOK + bib * BLK_ITEMS + w * (IPT * 32) + it * 32 + lane]);
    {
        const unsigned* cnt = g_cnt1 + seg * CNT_SEG;
#pragma unroll
        for (int k = 0; k < CPT; k++) v[k] = __ldcg(&cnt[tid * CPT + k]);
    }
    rank_items(e, 24, w, lane, whist, dg, rk);
    pass_finish(e, dg, rk, v, bib, w, lane, tid, g_e0 + seg * NTOK, nullptr,
                g_cnt2 + seg * CNT_SEG, 32, whist, wsum);

    seg_arrive(seg); seg_wait(seg, base, 4);

    // ---- Phase E: pass 2 — write only the inverse permutation (idx -> pos) ----
#pragma unroll
    for (int it = 0; it < IPT; it++)
        e[it] = __ldcg(&g_e0[seg * NTOK + bib * BLK_ITEMS + w * (IPT * 32) + it * 32 + lane]);
    {
        const unsigned* cnt = g_cnt2 + seg * CNT_SEG;
#pragma unroll
        for (int k = 0; k < CPT; k++) v[k] = __ldcg(&cnt[tid * CPT + k]);
    }
    rank_items(e, 32, w, lane, whist, dg, rk);
    pass_finish(e, dg, rk, v, bib, w, lane, tid, nullptr, g_inv + seg * NTOK,
                nullptr, 0, whist, wsum);

    if (bib == 0 && tid == 0) g_bases[seg * 32] = base + 4u * NBLK_SEG;
}

// ---------------- scatter: coalesced row reads, permuted row writes ----------------
__global__ void scatter_kernel(const float* __restrict__ lidar_tokens,
                               const float* __restrict__ img_tokens,
                               const unsigned char* __restrict__ lmask,
                               const unsigned char* __restrict__ imask,
                               float* __restrict__ out, int out_size) {
    int gid = blockIdx.x * blockDim.x + threadIdx.x;   // TOTAL*8 threads
    int r = gid >> 3;            // source row (global)
    int c = gid & 7;
    if (r >= TOTAL) return;
    int seg = r / NTOK, i = r % NTOK;                  // local source index
    unsigned pos = g_inv[r];                           // sorted position within segment
    size_t gpos = (size_t)seg * NTOK + pos;

    const float4* src;
    if (i < NLID)
        src = (const float4*)(lidar_tokens + ((size_t)seg * NLID + i) * C);
    else
        src = (const float4*)(img_tokens + ((size_t)seg * NIMG + (i - NLID)) * C);
    float4* d = (float4*)out + gpos * 64;
#pragma unroll
    for (int k = 0; k < 8; k++)
        d[c + 8 * k] = src[c + 8 * k];                 // coalesced read, permuted write

    if (c == 0) {
        size_t idx_base  = (size_t)TOTAL * C;
        size_t mask_base = idx_base + TOTAL;
        out[idx_base + gpos] = (float)i;
        bool m = (i < NLID) ? (lmask[(size_t)seg * NLID + i] != 0)
                            : (imask[(size_t)seg * NIMG + (i - NLID)] != 0);
        out[mask_base + gpos] = m ? 1.0f : 0.0f;
        if (r == 0) {
            size_t tail = mask_base + TOTAL;
            if ((size_t)out_size >= tail + 2) {
                out[tail + 0] = 16384.0f;
                out[tail + 1] = 1.0f;
            }
        }
    }
}

// ---------------- launch ----------------
extern "C" void kernel_launch(void* const* d_in, const int* in_sizes, int n_in,
                              void* d_out, int out_size) {
    const float* lidar_tokens = (const float*)d_in[0];
    const float* lidar_coords = (const float*)d_in[1];
    const float* img_tokens   = (const float*)d_in[2];
    const float* img_kuvd     = (const float*)d_in[3];
    const float* Km           = (const float*)d_in[4];
    const float* Tm           = (const float*)d_in[5];
    const float* Rm           = (const float*)d_in[6];
    const float* ptrans       = (const float*)d_in[7];
    const unsigned char* lm   = (const unsigned char*)d_in[8];
    const unsigned char* im   = (const unsigned char*)d_in[9];
    float* out = (float*)d_out;

    mega_kernel<<<NBLKS, STHR>>>(lidar_coords, img_kuvd, Km, Tm, Rm, ptrans, lm, im);
    scatter_kernel<<<(TOTAL * 8) / 256, 256>>>(lidar_tokens, img_tokens, lm, im,
                                               out, out_size);
}